// round 16
// baseline (speedup 1.0000x reference)
#include <cuda_runtime.h>
#include <cuda_fp16.h>
#include <math.h>
#include <stdint.h>

// ---------------- problem constants ----------------
#define DIMX     512
#define INTER    64
#define NSH      2
#define NROUTED  64
#define NEXP     66
#define TOPK     6
#define KSLOT    8
#define NTOK     1024
#define NSLOT    (NTOK * KSLOT)
#define TILE_M   32
#define MAXTILES 320
#define ECAP     1024

// ---------------- PTX helpers (sm_80-level only) ----------------
__device__ __forceinline__ uint32_t smem_u32(const void* p) {
    uint32_t a;
    asm("{ .reg .u64 t; cvta.to.shared.u64 t, %1; cvt.u32.u64 %0, t; }" : "=r"(a) : "l"(p));
    return a;
}
__device__ __forceinline__ void cp16(uint32_t sdst, const void* gsrc) {
    asm volatile("cp.async.cg.shared.global [%0], [%1], 16;" :: "r"(sdst), "l"(gsrc));
}
__device__ __forceinline__ void cp_commit() { asm volatile("cp.async.commit_group;"); }
template<int N> __device__ __forceinline__ void cp_wait() {
    asm volatile("cp.async.wait_group %0;" :: "n"(N));
}
__device__ __forceinline__ void ldsm4(uint32_t& r0, uint32_t& r1, uint32_t& r2, uint32_t& r3,
                                      uint32_t addr) {
    asm volatile("ldmatrix.sync.aligned.m8n8.x4.shared.b16 {%0,%1,%2,%3}, [%4];"
                 : "=r"(r0), "=r"(r1), "=r"(r2), "=r"(r3) : "r"(addr));
}
__device__ __forceinline__ void ldsm4t(uint32_t& r0, uint32_t& r1, uint32_t& r2, uint32_t& r3,
                                       uint32_t addr) {
    asm volatile("ldmatrix.sync.aligned.m8n8.x4.trans.shared.b16 {%0,%1,%2,%3}, [%4];"
                 : "=r"(r0), "=r"(r1), "=r"(r2), "=r"(r3) : "r"(addr));
}
__device__ __forceinline__ void mma_fp16(float* c, const uint32_t* a, const uint32_t* b) {
    asm volatile(
        "mma.sync.aligned.m16n8k16.row.col.f32.f16.f16.f32 "
        "{%0,%1,%2,%3}, {%4,%5,%6,%7}, {%8,%9}, {%0,%1,%2,%3};"
        : "+f"(c[0]), "+f"(c[1]), "+f"(c[2]), "+f"(c[3])
        : "r"(a[0]), "r"(a[1]), "r"(a[2]), "r"(a[3]), "r"(b[0]), "r"(b[1]));
}

// ---------------- device scratch (zero-initialized at module load) ----------------
__device__ int   g_eidx[NSLOT];
__device__ float g_wt[NSLOT];
__device__ int   g_counts[NEXP];       // invariant: zero at every kernel_launch entry
__device__ int   g_perm[NEXP * ECAP];
__device__ __half g_slot_out[(size_t)NSLOT * DIMX];   // 8 MB fp16 scratch

__device__ __half g_xhi[NTOK * DIMX];
__device__ __half g_xlo[NTOK * DIMX];
__device__ __half g_w13h[(size_t)NEXP * DIMX * 128];   // [e][k=512][n=128 (w1|w3)] fp16
__device__ __half g_w2h[(size_t)NEXP * INTER * DIMX];  // [e][j=64][d=512] fp16 (source layout)

// ---------------- kernel A: fused streaming prep + gate ----------------
// blocks [0,128): split x ; [128,656): w1 cvt ; [656,1184): w3 cvt ;
// [1184,1712): w2 cvt ; [1712,1744): gate (writes g_perm directly)
__global__ __launch_bounds__(256) void prepgate_kernel(
    const float* __restrict__ x, const float* __restrict__ w1,
    const float* __restrict__ w3, const float* __restrict__ w2,
    const float* __restrict__ gw, const float* __restrict__ bias)
{
    int blk = blockIdx.x;
    int tid = threadIdx.x;

    if (blk < 128) {                        // ---- split x into fp16 hi/lo (16 f/thread) ----
        int base = (blk * 256 + tid) * 16;
        #pragma unroll
        for (int u = 0; u < 4; u++) {
            float4 v = *reinterpret_cast<const float4*>(x + base + u * 4);
            __half h0 = __float2half_rn(v.x), h1 = __float2half_rn(v.y);
            __half h2 = __float2half_rn(v.z), h3 = __float2half_rn(v.w);
            __half l0 = __float2half_rn(v.x - __half2float(h0));
            __half l1 = __float2half_rn(v.y - __half2float(h1));
            __half l2 = __float2half_rn(v.z - __half2float(h2));
            __half l3 = __float2half_rn(v.w - __half2float(h3));
            *reinterpret_cast<__half2*>(g_xhi + base + u*4)     = __halves2half2(h0, h1);
            *reinterpret_cast<__half2*>(g_xhi + base + u*4 + 2) = __halves2half2(h2, h3);
            *reinterpret_cast<__half2*>(g_xlo + base + u*4)     = __halves2half2(l0, l1);
            *reinterpret_cast<__half2*>(g_xlo + base + u*4 + 2) = __halves2half2(l2, l3);
        }
        return;
    }
    if (blk < 1184) {                       // ---- w1/w3 -> g_w13h [row k][128 n] ----
        int sel = (blk >= 656);             // 0: w1 -> cols 0..63 ; 1: w3 -> cols 64..127
        const float* src = sel ? w3 : w1;
        int base = ((blk - (sel ? 656 : 128)) * 256 + tid) * 16;   // flat float idx
        int row = base >> 6;                // global k-row (e*512 + k)
        int j   = base & 63;                // 0,16,32,48
        __half* dst = g_w13h + (size_t)row * 128 + sel * 64 + j;
        #pragma unroll
        for (int u = 0; u < 4; u++) {
            float4 v = *reinterpret_cast<const float4*>(src + base + u * 4);
            *reinterpret_cast<__half2*>(dst + u*4)     = __floats2half2_rn(v.x, v.y);
            *reinterpret_cast<__half2*>(dst + u*4 + 2) = __floats2half2_rn(v.z, v.w);
        }
        return;
    }
    if (blk < 1712) {                       // ---- w2 -> g_w2h (same layout, cvt only) ----
        int base = ((blk - 1184) * 256 + tid) * 16;
        #pragma unroll
        for (int u = 0; u < 4; u++) {
            float4 v = *reinterpret_cast<const float4*>(w2 + base + u * 4);
            *reinterpret_cast<__half2*>(g_w2h + base + u*4)     = __floats2half2_rn(v.x, v.y);
            *reinterpret_cast<__half2*>(g_w2h + base + u*4 + 2) = __floats2half2_rn(v.z, v.w);
        }
        return;
    }

    // ---------------- gate branch (blocks 1712..1743) ----------------
    {
        __shared__ float Xs[32][32];
        __shared__ float Gs[32][65];
        __shared__ float S[32][66];

        int tok0 = (blk - 1712) * 32;
        int tg   = tid >> 5;
        int lane = tid & 31;

        float acc[4][2] = {};

        for (int k0 = 0; k0 < DIMX; k0 += 32) {
            {
                int r = tid >> 3;
                int c = (tid & 7) * 4;
                float4 v = *reinterpret_cast<const float4*>(&x[(size_t)(tok0 + r) * DIMX + k0 + c]);
                Xs[r][c] = v.x; Xs[r][c+1] = v.y; Xs[r][c+2] = v.z; Xs[r][c+3] = v.w;
            }
            {
                int e  = tid >> 2;
                int kk = (tid & 3) * 8;
                float4 a = *reinterpret_cast<const float4*>(&gw[(size_t)e * DIMX + k0 + kk]);
                float4 b = *reinterpret_cast<const float4*>(&gw[(size_t)e * DIMX + k0 + kk + 4]);
                Gs[kk+0][e] = a.x; Gs[kk+1][e] = a.y; Gs[kk+2][e] = a.z; Gs[kk+3][e] = a.w;
                Gs[kk+4][e] = b.x; Gs[kk+5][e] = b.y; Gs[kk+6][e] = b.z; Gs[kk+7][e] = b.w;
            }
            __syncthreads();
            #pragma unroll
            for (int kk = 0; kk < 32; kk++) {
                float g0 = Gs[kk][lane], g1 = Gs[kk][lane + 32];
                #pragma unroll
                for (int i = 0; i < 4; i++) {
                    float xv = Xs[tg * 4 + i][kk];
                    acc[i][0] = fmaf(xv, g0, acc[i][0]);
                    acc[i][1] = fmaf(xv, g1, acc[i][1]);
                }
            }
            __syncthreads();
        }
        #pragma unroll
        for (int i = 0; i < 4; i++) {
            S[tg * 4 + i][lane]      = acc[i][0];
            S[tg * 4 + i][lane + 32] = acc[i][1];
        }
        __syncthreads();

        float b0 = bias[lane], b1 = bias[lane + 32];
        for (int i = 0; i < 4; i++) {
            int t = tg * 4 + i;
            float s0 = S[t][lane], s1 = S[t][lane + 32];
            float mx = fmaxf(s0, s1);
            #pragma unroll
            for (int o = 16; o > 0; o >>= 1) mx = fmaxf(mx, __shfl_xor_sync(0xffffffffu, mx, o));
            float e0 = expf(s0 - mx), e1 = expf(s1 - mx);
            float z = e0 + e1;
            #pragma unroll
            for (int o = 16; o > 0; o >>= 1) z += __shfl_xor_sync(0xffffffffu, z, o);
            float inv = 1.0f / z;
            float p0 = e0 * inv, p1 = e1 * inv;
            float k0v = p0 + b0, k1v = p1 + b1;
            int gt = tok0 + t;
            for (int r = 0; r < TOPK; r++) {
                float key, pv; int idx;
                if (k0v >= k1v) { key = k0v; pv = p0; idx = lane; }
                else            { key = k1v; pv = p1; idx = lane + 32; }
                #pragma unroll
                for (int o = 16; o > 0; o >>= 1) {
                    float ok = __shfl_xor_sync(0xffffffffu, key, o);
                    float op = __shfl_xor_sync(0xffffffffu, pv,  o);
                    int   oi = __shfl_xor_sync(0xffffffffu, idx, o);
                    if (ok > key || (ok == key && oi < idx)) { key = ok; pv = op; idx = oi; }
                }
                if (lane == 0) {
                    int slot = gt * KSLOT + NSH + r;
                    int e = idx + NSH;
                    g_eidx[slot] = e;
                    g_wt  [slot] = pv;
                    int pos = atomicAdd(&g_counts[e], 1);
                    g_perm[e * ECAP + pos] = slot;
                }
                if (idx == lane)           k0v = -INFINITY;
                else if (idx == lane + 32) k1v = -INFINITY;
            }
            if (lane < NSH) {
                int slot = gt * KSLOT + lane;
                g_eidx[slot] = lane;
                g_wt  [slot] = 1.0f;
                g_perm[lane * ECAP + gt] = slot;
            }
        }
    }
}

// ---------------- kernel 4: grouped expert FFN, fp16 2-pass mma.sync ----------------
// B operands staged in [k-rows][256B] layout, loaded with ldmatrix.trans.
__global__ void __launch_bounds__(256, 2) ffn_mma_kernel()
{
    extern __shared__ __align__(16) char dyn[];
    __shared__ int   toks[TILE_M];
    __shared__ float wts[TILE_M];
    __shared__ int   slots[TILE_M];
    __shared__ int   cnt_sm[NEXP];
    __shared__ int   s_e, s_j, s_m;

    int bid = blockIdx.x;
    int tid = threadIdx.x, wid = tid >> 5, lane = tid & 31;

    if (tid < NEXP) cnt_sm[tid] = (tid < NSH) ? NTOK : g_counts[tid];
    __syncthreads();
    if (tid == 0) {
        int accn = 0, fe = -1, fj = 0, fm = 0;
        for (int ee = 0; ee < NEXP; ee++) {
            int c = cnt_sm[ee];
            int nt = (c + TILE_M - 1) >> 5;
            if (bid < accn + nt) {
                fe = ee; fj = (bid - accn) * TILE_M;
                fm = min(TILE_M, c - fj);
                break;
            }
            accn += nt;
        }
        s_e = fe; s_j = fj; s_m = fm;
    }
    __syncthreads();
    int e = s_e, m = s_m;
    if (e < 0) return;
    int p0 = e * ECAP + s_j;

    int mg = wid >> 2;          // token half 0/1
    int nw = wid & 3;           // N slice

    uint32_t sb = smem_u32(dyn);
    uint32_t Ah[2] = { sb,          sb + 4096  };
    uint32_t Al[2] = { sb + 8192,   sb + 12288 };
    uint32_t Bh[2] = { sb + 16384,  sb + 32768 };
    uint32_t Gh = sb + 49152, Gl = sb + 53248;

    if (tid < TILE_M) {
        int i = (tid < m) ? g_perm[p0 + tid] : g_perm[p0];
        slots[tid] = i; toks[tid] = i >> 3; wts[tid] = g_wt[i];
    }
    __syncthreads();

    const __half* w13 = g_w13h + (size_t)e * DIMX * 128;   // [k=512][n=128]
    const __half* w2e = g_w2h  + (size_t)e * INTER * DIMX; // [j=64][d=512]

    // A tile [32 tok][64 k], 128B rows (unchanged)
    auto stage_A = [&](const __half* src, uint32_t dst, int kb) {
        int row = tid >> 3, c = tid & 7;
        cp16(dst + row * 128 + ((c ^ (row & 7)) << 4),
             src + (size_t)toks[row] * DIMX + kb * 64 + c * 8);
    };
    // B tile [64 k-rows][128 n] = 256B rows; chunk c in 0..15, swizzle c ^ (row&7)
    auto stage_B = [&](const __half* src, uint32_t dst, int kb) {
        #pragma unroll
        for (int q = 0; q < 4; q++) {
            int idx = tid + q * 256;              // 0..1023
            int row = idx >> 4, c = idx & 15;
            cp16(dst + row * 256 + (((uint32_t)(c ^ (row & 7))) << 4),
                 src + (size_t)(kb * 64 + row) * 128 + c * 8);
        }
    };
    // W2 tile [64 j-rows][128 d] per chunk
    auto stage_W2 = [&](const __half* src, uint32_t dst, int chunk) {
        #pragma unroll
        for (int q = 0; q < 4; q++) {
            int idx = tid + q * 256;
            int row = idx >> 4, c = idx & 15;
            cp16(dst + row * 256 + (((uint32_t)(c ^ (row & 7))) << 4),
                 src + (size_t)row * DIMX + chunk * 128 + c * 8);
        }
    };

    auto addrA = [&](uint32_t base, int mt, int k0) {
        int row = mt * 16 + (lane & 15);
        int kc  = (k0 >> 3) + (lane >> 4);
        return base + row * 128 + (((uint32_t)kc ^ (row & 7)) << 4);
    };
    // trans B: m0 rows k0..+7 col nb; m1 rows k0+8..15 col nb; m2/m3 at col nb+8
    auto addrBT = [&](uint32_t base, int nb, int k0) {
        int row = k0 + (lane & 7) + (((lane >> 3) & 1) << 3);
        int c   = (nb >> 3) + ((lane >> 4) << 0) * 0 + (lane >> 4);  // chunk = nb/8 + (lane>>4)
        return base + row * 256 + (((uint32_t)(c ^ (row & 7))) << 4);
    };

    // ---- h-stage ----
    float acc[4][4] = {};

    stage_A(g_xhi, Ah[0], 0); stage_A(g_xlo, Al[0], 0);
    stage_B(w13, Bh[0], 0);
    cp_commit();

    #pragma unroll 1
    for (int kb = 0; kb < 8; kb++) {
        int b = kb & 1;
        if (kb + 1 < 8) {
            int nb = b ^ 1;
            stage_A(g_xhi, Ah[nb], kb + 1); stage_A(g_xlo, Al[nb], kb + 1);
            stage_B(w13, Bh[nb], kb + 1);
            cp_commit();
            cp_wait<1>();
        } else {
            cp_wait<0>();
        }
        __syncthreads();

        #pragma unroll
        for (int pass = 0; pass < 2; pass++) {
            uint32_t Abase = pass ? Al[b] : Ah[b];
            uint32_t Bbase = Bh[b];
            #pragma unroll
            for (int ks = 0; ks < 4; ks++) {
                int k0 = ks * 16;
                uint32_t a[4], bt[4][2];
                ldsm4(a[0], a[1], a[2], a[3], addrA(Abase, mg, k0));
                {
                    uint32_t r0, r1, r2, r3;
                    ldsm4t(r0, r1, r2, r3, addrBT(Bbase, nw * 16, k0));
                    bt[0][0] = r0; bt[0][1] = r1; bt[1][0] = r2; bt[1][1] = r3;
                    ldsm4t(r0, r1, r2, r3, addrBT(Bbase, 64 + nw * 16, k0));
                    bt[2][0] = r0; bt[2][1] = r1; bt[3][0] = r2; bt[3][1] = r3;
                }
                #pragma unroll
                for (int nt = 0; nt < 4; nt++)
                    mma_fp16(acc[nt], a, bt[nt]);
            }
        }
        __syncthreads();
    }

    // prefetch W2 chunk 0 while epilogue runs
    stage_W2(w2e, Bh[0], 0);
    cp_commit();

    // ---- epilogue: g = silu(h1)*h3 -> Gh/Gl fp16 swizzled (A-layout, unchanged) ----
    {
        int rbase = lane >> 2, cbase = (lane & 3) * 2;
        #pragma unroll
        for (int p = 0; p < 2; p++) {
            const float* h1 = acc[p];
            const float* h3 = acc[p + 2];
            #pragma unroll
            for (int half = 0; half < 2; half++) {
                int row = mg * 16 + rbase + half * 8;
                float v0 = h1[half * 2], v1 = h1[half * 2 + 1];
                float g0 = v0 / (1.0f + __expf(-v0)) * h3[half * 2];
                float g1 = v1 / (1.0f + __expf(-v1)) * h3[half * 2 + 1];
                __half h0 = __float2half_rn(g0), h1h = __float2half_rn(g1);
                __half l0 = __float2half_rn(g0 - __half2float(h0));
                __half l1 = __float2half_rn(g1 - __half2float(h1h));
                int j = nw * 16 + p * 8 + cbase;
                uint32_t off = row * 128 + (((uint32_t)(j >> 3) ^ (row & 7)) << 4)
                               + (j & 7) * 2;
                *reinterpret_cast<__half2*>((char*)dyn + (Gh - sb) + off) = __halves2half2(h0, h1h);
                *reinterpret_cast<__half2*>((char*)dyn + (Gl - sb) + off) = __halves2half2(l0, l1);
            }
        }
    }
    __syncthreads();

    // ---- W2 stage: 4 chunks of 128 d, double-buffered, 2 passes ----
    int rbase = lane >> 2, cbase = (lane & 3) * 2;
    #pragma unroll 1
    for (int c = 0; c < 4; c++) {
        int b = c & 1;
        if (c + 1 < 4) {
            int nb = b ^ 1;
            stage_W2(w2e, Bh[nb], c + 1);
            cp_commit();
            cp_wait<1>();
        } else {
            cp_wait<0>();
        }
        __syncthreads();

        float oacc[4][4] = {};
        #pragma unroll
        for (int pass = 0; pass < 2; pass++) {
            uint32_t Abase = pass ? Gl : Gh;
            uint32_t Bbase = Bh[b];
            #pragma unroll
            for (int ks = 0; ks < 4; ks++) {
                int k0 = ks * 16;
                uint32_t a[4], bt[4][2];
                ldsm4(a[0], a[1], a[2], a[3], addrA(Abase, mg, k0));
                {
                    uint32_t r0, r1, r2, r3;
                    ldsm4t(r0, r1, r2, r3, addrBT(Bbase, nw * 32, k0));
                    bt[0][0] = r0; bt[0][1] = r1; bt[1][0] = r2; bt[1][1] = r3;
                    ldsm4t(r0, r1, r2, r3, addrBT(Bbase, nw * 32 + 16, k0));
                    bt[2][0] = r0; bt[2][1] = r1; bt[3][0] = r2; bt[3][1] = r3;
                }
                #pragma unroll
                for (int nt = 0; nt < 4; nt++)
                    mma_fp16(oacc[nt], a, bt[nt]);
            }
        }
        #pragma unroll
        for (int half = 0; half < 2; half++) {
            int r = mg * 16 + rbase + half * 8;
            if (r < m) {
                float wt = wts[r];
                __half* orow = g_slot_out + (size_t)slots[r] * DIMX;
                #pragma unroll
                for (int nt = 0; nt < 4; nt++) {
                    int col = c * 128 + nw * 32 + nt * 8 + cbase;
                    *reinterpret_cast<__half2*>(orow + col) =
                        __floats2half2_rn(oacc[nt][half * 2]     * wt,
                                          oacc[nt][half * 2 + 1] * wt);
                }
            }
        }
        __syncthreads();
    }
}

// ---------------- kernel 5: combine (fp16 slots) + counts reset ----------------
__global__ void combine_kernel(float* __restrict__ out) {
    int i = blockIdx.x * 256 + threadIdx.x;
    if (blockIdx.x == 0 && threadIdx.x < NEXP) g_counts[threadIdx.x] = 0;
    if (i >= NTOK * DIMX / 4) return;
    int t = i >> 7;
    int d4 = i & (DIMX/4 - 1);
    float4 s = make_float4(0.f, 0.f, 0.f, 0.f);
    #pragma unroll
    for (int sl = 0; sl < KSLOT; sl++) {
        const __half2* p = reinterpret_cast<const __half2*>(
            &g_slot_out[((size_t)(t * KSLOT + sl)) * DIMX + d4 * 4]);
        float2 a = __half22float2(p[0]);
        float2 b = __half22float2(p[1]);
        s.x += a.x; s.y += a.y; s.z += b.x; s.w += b.y;
    }
    reinterpret_cast<float4*>(out)[i] = s;
}

// ---------------- launch ----------------
extern "C" void kernel_launch(void* const* d_in, const int* in_sizes, int n_in,
                              void* d_out, int out_size) {
    const float* x  = (const float*)d_in[0];
    const float* gw = (const float*)d_in[1];
    const float* gb = (const float*)d_in[2];
    const float* w1 = (const float*)d_in[3];
    const float* w2 = (const float*)d_in[4];
    const float* w3 = (const float*)d_in[5];
    float* out = (float*)d_out;

    const int ffn_smem = 57344;   // A 16K + B 32K + G 8K
    cudaFuncSetAttribute(ffn_mma_kernel,
                         cudaFuncAttributeMaxDynamicSharedMemorySize, ffn_smem);

    prepgate_kernel<<<1744, 256>>>(x, w1, w3, w2, gw, gb);
    ffn_mma_kernel<<<MAXTILES, 256, ffn_smem>>>();
    combine_kernel<<<(NTOK * DIMX / 4) / 256, 256>>>(out);
}

// round 17
// speedup vs baseline: 1.3353x; 1.3353x over previous
#include <cuda_runtime.h>
#include <cuda_fp16.h>
#include <math.h>
#include <stdint.h>

// ---------------- problem constants ----------------
#define DIMX     512
#define INTER    64
#define NSH      2
#define NROUTED  64
#define NEXP     66
#define TOPK     6
#define KSLOT    8
#define NTOK     1024
#define NSLOT    (NTOK * KSLOT)
#define TILE_M   32
#define MAXTILES 320
#define ECAP     1024          // fixed per-expert segment capacity in g_perm

// ---------------- PTX helpers (sm_80-level only) ----------------
__device__ __forceinline__ uint32_t smem_u32(const void* p) {
    uint32_t a;
    asm("{ .reg .u64 t; cvta.to.shared.u64 t, %1; cvt.u32.u64 %0, t; }" : "=r"(a) : "l"(p));
    return a;
}
__device__ __forceinline__ void cp16(uint32_t sdst, const void* gsrc) {
    asm volatile("cp.async.cg.shared.global [%0], [%1], 16;" :: "r"(sdst), "l"(gsrc));
}
__device__ __forceinline__ void cp_commit() { asm volatile("cp.async.commit_group;"); }
template<int N> __device__ __forceinline__ void cp_wait() {
    asm volatile("cp.async.wait_group %0;" :: "n"(N));
}
__device__ __forceinline__ void ldsm4(uint32_t& r0, uint32_t& r1, uint32_t& r2, uint32_t& r3,
                                      uint32_t addr) {
    asm volatile("ldmatrix.sync.aligned.m8n8.x4.shared.b16 {%0,%1,%2,%3}, [%4];"
                 : "=r"(r0), "=r"(r1), "=r"(r2), "=r"(r3) : "r"(addr));
}
__device__ __forceinline__ void mma_fp16(float* c, const uint32_t* a, const uint32_t* b) {
    asm volatile(
        "mma.sync.aligned.m16n8k16.row.col.f32.f16.f16.f32 "
        "{%0,%1,%2,%3}, {%4,%5,%6,%7}, {%8,%9}, {%0,%1,%2,%3};"
        : "+f"(c[0]), "+f"(c[1]), "+f"(c[2]), "+f"(c[3])
        : "r"(a[0]), "r"(a[1]), "r"(a[2]), "r"(a[3]), "r"(b[0]), "r"(b[1]));
}

// ---------------- device scratch (zero-initialized at module load) ----------------
__device__ int   g_eidx[NSLOT];
__device__ float g_wt[NSLOT];
__device__ int   g_pos[NSLOT];
__device__ int   g_counts[NEXP];       // invariant: zero at every kernel_launch entry
__device__ int   g_perm[NEXP * ECAP];
__device__ int4  g_tiles[MAXTILES];
__device__ int   g_ntiles;
__device__ __half g_slot_out[(size_t)NSLOT * DIMX];   // 8 MB fp16 scratch

__device__ __half g_xhi[NTOK * DIMX];
__device__ __half g_xlo[NTOK * DIMX];
__device__ __half g_w13h[(size_t)NEXP * 128 * DIMX];   // [e][n=128(j1|j3)][k=512] fp16
__device__ __half g_w2h[(size_t)NEXP * DIMX * INTER];  // [e][d=512][j=64] fp16

// ---------------- kernel A: fused gate + prep ----------------
// blocks [0,32): gate (scheduled FIRST -> overlaps prep streaming, no tail)
// blocks [32,544): split x ; [544,1072): w13 cvt ; [1072,1600): w2 cvt
__global__ __launch_bounds__(256) void prepgate_kernel(
    const float* __restrict__ x, const float* __restrict__ w1,
    const float* __restrict__ w3, const float* __restrict__ w2,
    const float* __restrict__ gw, const float* __restrict__ bias)
{
    int blk = blockIdx.x;
    int tid = threadIdx.x;

    if (blk >= 32 && blk < 544) {           // ---- split x into fp16 hi/lo ----
        int i = ((blk - 32) * 256 + tid) * 4;
        float4 v = *reinterpret_cast<const float4*>(x + i);
        __half h0 = __float2half_rn(v.x), h1 = __float2half_rn(v.y);
        __half h2 = __float2half_rn(v.z), h3 = __float2half_rn(v.w);
        __half l0 = __float2half_rn(v.x - __half2float(h0));
        __half l1 = __float2half_rn(v.y - __half2float(h1));
        __half l2 = __float2half_rn(v.z - __half2float(h2));
        __half l3 = __float2half_rn(v.w - __half2float(h3));
        *reinterpret_cast<__half2*>(g_xhi + i)     = __halves2half2(h0, h1);
        *reinterpret_cast<__half2*>(g_xhi + i + 2) = __halves2half2(h2, h3);
        *reinterpret_cast<__half2*>(g_xlo + i)     = __halves2half2(l0, l1);
        *reinterpret_cast<__half2*>(g_xlo + i + 2) = __halves2half2(l2, l3);
        return;
    }
    if (blk >= 544 && blk < 1072) {         // ---- transpose + cvt W1||W3 ----
        int id = blk - 544;
        int e = id >> 3, kb = id & 7;
        __shared__ float T1[64][65], T3[64][65];
        #pragma unroll
        for (int q = 0; q < 16; q++) {
            int idx = tid + q * 256;
            int kk = idx >> 6, j = idx & 63;
            size_t s = ((size_t)e * DIMX + kb * 64 + kk) * INTER + j;
            T1[kk][j] = w1[s];
            T3[kk][j] = w3[s];
        }
        __syncthreads();
        #pragma unroll
        for (int q = 0; q < 16; q++) {
            int idx = tid + q * 256;
            int j = idx >> 6, kk = idx & 63;
            size_t o1 = ((size_t)e * 128 + j) * DIMX + kb * 64 + kk;
            size_t o3 = ((size_t)e * 128 + 64 + j) * DIMX + kb * 64 + kk;
            g_w13h[o1] = __float2half_rn(T1[kk][j]);
            g_w13h[o3] = __float2half_rn(T3[kk][j]);
        }
        return;
    }
    if (blk >= 1072) {                      // ---- transpose + cvt W2 ----
        int id = blk - 1072;
        int e = id >> 3, db = id & 7;
        __shared__ float T[64][65];
        #pragma unroll
        for (int q = 0; q < 16; q++) {
            int idx = tid + q * 256;
            int j = idx >> 6, d = idx & 63;
            T[j][d] = w2[((size_t)e * INTER + j) * DIMX + db * 64 + d];
        }
        __syncthreads();
        #pragma unroll
        for (int q = 0; q < 16; q++) {
            int idx = tid + q * 256;
            int d = idx >> 6, j = idx & 63;
            size_t o = ((size_t)e * DIMX + db * 64 + d) * INTER + j;
            g_w2h[o] = __float2half_rn(T[j][d]);
        }
        return;
    }

    // ---------------- gate branch (blocks 0..31, scheduled first) ----------------
    {
        __shared__ float Xs[32][32];
        __shared__ float Gs[32][65];
        __shared__ float S[32][66];

        int tok0 = blk * 32;
        int tg   = tid >> 5;
        int lane = tid & 31;

        float acc[4][2] = {};

        for (int k0 = 0; k0 < DIMX; k0 += 32) {
            {
                int r = tid >> 3;
                int c = (tid & 7) * 4;
                float4 v = *reinterpret_cast<const float4*>(&x[(size_t)(tok0 + r) * DIMX + k0 + c]);
                Xs[r][c] = v.x; Xs[r][c+1] = v.y; Xs[r][c+2] = v.z; Xs[r][c+3] = v.w;
            }
            {
                int e  = tid >> 2;
                int kk = (tid & 3) * 8;
                float4 a = *reinterpret_cast<const float4*>(&gw[(size_t)e * DIMX + k0 + kk]);
                float4 b = *reinterpret_cast<const float4*>(&gw[(size_t)e * DIMX + k0 + kk + 4]);
                Gs[kk+0][e] = a.x; Gs[kk+1][e] = a.y; Gs[kk+2][e] = a.z; Gs[kk+3][e] = a.w;
                Gs[kk+4][e] = b.x; Gs[kk+5][e] = b.y; Gs[kk+6][e] = b.z; Gs[kk+7][e] = b.w;
            }
            __syncthreads();
            #pragma unroll
            for (int kk = 0; kk < 32; kk++) {
                float g0 = Gs[kk][lane], g1 = Gs[kk][lane + 32];
                #pragma unroll
                for (int i = 0; i < 4; i++) {
                    float xv = Xs[tg * 4 + i][kk];
                    acc[i][0] = fmaf(xv, g0, acc[i][0]);
                    acc[i][1] = fmaf(xv, g1, acc[i][1]);
                }
            }
            __syncthreads();
        }
        #pragma unroll
        for (int i = 0; i < 4; i++) {
            S[tg * 4 + i][lane]      = acc[i][0];
            S[tg * 4 + i][lane + 32] = acc[i][1];
        }
        __syncthreads();

        float b0 = bias[lane], b1 = bias[lane + 32];
        for (int i = 0; i < 4; i++) {
            int t = tg * 4 + i;
            float s0 = S[t][lane], s1 = S[t][lane + 32];
            float mx = fmaxf(s0, s1);
            #pragma unroll
            for (int o = 16; o > 0; o >>= 1) mx = fmaxf(mx, __shfl_xor_sync(0xffffffffu, mx, o));
            float e0 = expf(s0 - mx), e1 = expf(s1 - mx);
            float z = e0 + e1;
            #pragma unroll
            for (int o = 16; o > 0; o >>= 1) z += __shfl_xor_sync(0xffffffffu, z, o);
            float inv = 1.0f / z;
            float p0 = e0 * inv, p1 = e1 * inv;
            float k0v = p0 + b0, k1v = p1 + b1;
            int gt = tok0 + t;
            for (int r = 0; r < TOPK; r++) {
                float key, pv; int idx;
                if (k0v >= k1v) { key = k0v; pv = p0; idx = lane; }
                else            { key = k1v; pv = p1; idx = lane + 32; }
                #pragma unroll
                for (int o = 16; o > 0; o >>= 1) {
                    float ok = __shfl_xor_sync(0xffffffffu, key, o);
                    float op = __shfl_xor_sync(0xffffffffu, pv,  o);
                    int   oi = __shfl_xor_sync(0xffffffffu, idx, o);
                    if (ok > key || (ok == key && oi < idx)) { key = ok; pv = op; idx = oi; }
                }
                if (lane == 0) {
                    int slot = gt * KSLOT + NSH + r;
                    g_eidx[slot] = idx + NSH;
                    g_wt  [slot] = pv;
                    g_pos [slot] = atomicAdd(&g_counts[idx + NSH], 1);
                }
                if (idx == lane)           k0v = -INFINITY;
                else if (idx == lane + 32) k1v = -INFINITY;
            }
            if (lane < NSH) {
                int slot = gt * KSLOT + lane;
                g_eidx[slot] = lane;
                g_wt  [slot] = 1.0f;
                g_pos [slot] = gt;
            }
        }
    }
}

// ---------------- kernel B: fused scatter + parallel scan (+counts reset) ----------------
__global__ void scatscan_kernel() {
    if (blockIdx.x < 32) {
        int i = blockIdx.x * 256 + threadIdx.x;
        int e = g_eidx[i];
        g_perm[e * ECAP + g_pos[i]] = i;
    } else {
        __shared__ int cnt[NEXP];
        __shared__ int pre[NEXP + 1];
        int t = threadIdx.x;
        if (t < NEXP) cnt[t] = (t < NSH) ? NTOK : g_counts[t];
        __syncthreads();
        if (t == 0) {
            int s = 0;
            for (int e = 0; e < NEXP; e++) {
                pre[e] = s;
                s += (cnt[e] + TILE_M - 1) / TILE_M;
            }
            g_ntiles = s;
        }
        __syncthreads();
        if (t < NEXP) {
            int base = pre[t], c = cnt[t];
            for (int j = 0, k = 0; j < c; j += TILE_M, k++)
                g_tiles[base + k] = make_int4(t, t * ECAP + j, min(TILE_M, c - j), 0);
            if (t >= NSH) g_counts[t] = 0;   // restore zero-invariant for next replay
        }
    }
}

// ---------------- kernel 4: grouped expert FFN, fp16 2-pass mma.sync (proven) ----------------
__global__ void __launch_bounds__(256, 2) ffn_mma_kernel()
{
    extern __shared__ __align__(16) char dyn[];
    __shared__ int   toks[TILE_M];
    __shared__ float wts[TILE_M];
    __shared__ int   slots[TILE_M];

    int bid = blockIdx.x;
    if (bid >= g_ntiles) return;
    int4 tl = g_tiles[bid];
    int e = tl.x, p0 = tl.y, m = tl.z;

    int tid = threadIdx.x, wid = tid >> 5, lane = tid & 31;
    int mg = wid >> 2;          // token half 0/1
    int nw = wid & 3;           // N slice

    uint32_t sb = smem_u32(dyn);
    uint32_t Ah[2] = { sb,          sb + 4096  };
    uint32_t Al[2] = { sb + 8192,   sb + 12288 };
    uint32_t Bh[2] = { sb + 16384,  sb + 32768 };
    uint32_t Gh = sb + 49152, Gl = sb + 53248;

    if (tid < TILE_M) {
        int i = (tid < m) ? g_perm[p0 + tid] : g_perm[p0];
        slots[tid] = i; toks[tid] = i >> 3; wts[tid] = g_wt[i];
    }
    __syncthreads();

    const __half* w13 = g_w13h + (size_t)e * 128 * DIMX;
    const __half* w2e = g_w2h  + (size_t)e * DIMX * INTER;

    auto stage_A = [&](const __half* src, uint32_t dst, int kb) {
        int row = tid >> 3, c = tid & 7;
        cp16(dst + row * 128 + ((c ^ (row & 7)) << 4),
             src + (size_t)toks[row] * DIMX + kb * 64 + c * 8);
    };
    auto stage_B = [&](const __half* src, uint32_t dst, int kb) {
        #pragma unroll
        for (int q = 0; q < 4; q++) {
            int idx = tid + q * 256;
            int row = idx >> 3, c = idx & 7;
            cp16(dst + row * 128 + ((c ^ (row & 7)) << 4),
                 src + (size_t)row * DIMX + kb * 64 + c * 8);
        }
    };
    auto stage_W2 = [&](const __half* src, uint32_t dst, int chunk) {
        #pragma unroll
        for (int q = 0; q < 4; q++) {
            int idx = tid + q * 256;
            int row = idx >> 3, c = idx & 7;
            cp16(dst + row * 128 + ((c ^ (row & 7)) << 4),
                 src + (size_t)(chunk * 128 + row) * INTER + c * 8);
        }
    };

    auto addrA = [&](uint32_t base, int mt, int k0) {
        int row = mt * 16 + (lane & 15);
        int kc  = (k0 >> 3) + (lane >> 4);
        return base + row * 128 + (((uint32_t)kc ^ (row & 7)) << 4);
    };
    auto addrB = [&](uint32_t base, int nb, int k0) {
        int row = nb + (lane & 7) + ((lane >> 4) << 3);
        int kc  = (k0 >> 3) + ((lane >> 3) & 1);
        return base + row * 128 + (((uint32_t)kc ^ (row & 7)) << 4);
    };

    // ---- h-stage ----
    float acc[4][4] = {};

    stage_A(g_xhi, Ah[0], 0); stage_A(g_xlo, Al[0], 0);
    stage_B(w13, Bh[0], 0);
    cp_commit();

    #pragma unroll 1
    for (int kb = 0; kb < 8; kb++) {
        int b = kb & 1;
        if (kb + 1 < 8) {
            int nb = b ^ 1;
            stage_A(g_xhi, Ah[nb], kb + 1); stage_A(g_xlo, Al[nb], kb + 1);
            stage_B(w13, Bh[nb], kb + 1);
            cp_commit();
            cp_wait<1>();
        } else {
            cp_wait<0>();
        }
        __syncthreads();

        #pragma unroll
        for (int pass = 0; pass < 2; pass++) {
            uint32_t Abase = pass ? Al[b] : Ah[b];
            uint32_t Bbase = Bh[b];
            #pragma unroll
            for (int ks = 0; ks < 4; ks++) {
                int k0 = ks * 16;
                uint32_t a[4], bt[4][2];
                ldsm4(a[0], a[1], a[2], a[3], addrA(Abase, mg, k0));
                {
                    uint32_t r0, r1, r2, r3;
                    ldsm4(r0, r1, r2, r3, addrB(Bbase, nw * 16, k0));
                    bt[0][0] = r0; bt[0][1] = r1; bt[1][0] = r2; bt[1][1] = r3;
                    ldsm4(r0, r1, r2, r3, addrB(Bbase, 64 + nw * 16, k0));
                    bt[2][0] = r0; bt[2][1] = r1; bt[3][0] = r2; bt[3][1] = r3;
                }
                #pragma unroll
                for (int nt = 0; nt < 4; nt++)
                    mma_fp16(acc[nt], a, bt[nt]);
            }
        }
        __syncthreads();
    }

    // prefetch W2 chunk 0 while epilogue runs
    stage_W2(w2e, Bh[0], 0);
    cp_commit();

    // ---- epilogue: g = silu(h1)*h3 -> Gh/Gl fp16 swizzled ----
    {
        int rbase = lane >> 2, cbase = (lane & 3) * 2;
        #pragma unroll
        for (int p = 0; p < 2; p++) {
            const float* h1 = acc[p];
            const float* h3 = acc[p + 2];
            #pragma unroll
            for (int half = 0; half < 2; half++) {
                int row = mg * 16 + rbase + half * 8;
                float v0 = h1[half * 2], v1 = h1[half * 2 + 1];
                float g0 = v0 / (1.0f + __expf(-v0)) * h3[half * 2];
                float g1 = v1 / (1.0f + __expf(-v1)) * h3[half * 2 + 1];
                __half h0 = __float2half_rn(g0), h1h = __float2half_rn(g1);
                __half l0 = __float2half_rn(g0 - __half2float(h0));
                __half l1 = __float2half_rn(g1 - __half2float(h1h));
                int j = nw * 16 + p * 8 + cbase;
                uint32_t off = row * 128 + (((uint32_t)(j >> 3) ^ (row & 7)) << 4)
                               + (j & 7) * 2;
                *reinterpret_cast<__half2*>((char*)dyn + (Gh - sb) + off) = __halves2half2(h0, h1h);
                *reinterpret_cast<__half2*>((char*)dyn + (Gl - sb) + off) = __halves2half2(l0, l1);
            }
        }
    }
    __syncthreads();

    // ---- W2 stage: 4 chunks of 128 d, double-buffered, 2 passes ----
    int rbase = lane >> 2, cbase = (lane & 3) * 2;
    #pragma unroll 1
    for (int c = 0; c < 4; c++) {
        int b = c & 1;
        if (c + 1 < 4) {
            int nb = b ^ 1;
            stage_W2(w2e, Bh[nb], c + 1);
            cp_commit();
            cp_wait<1>();
        } else {
            cp_wait<0>();
        }
        __syncthreads();

        float oacc[4][4] = {};
        #pragma unroll
        for (int pass = 0; pass < 2; pass++) {
            uint32_t Abase = pass ? Gl : Gh;
            uint32_t Bbase = Bh[b];
            #pragma unroll
            for (int ks = 0; ks < 4; ks++) {
                int k0 = ks * 16;
                uint32_t a[4], bt[4][2];
                ldsm4(a[0], a[1], a[2], a[3], addrA(Abase, mg, k0));
                {
                    uint32_t r0, r1, r2, r3;
                    ldsm4(r0, r1, r2, r3, addrB(Bbase, nw * 32, k0));
                    bt[0][0] = r0; bt[0][1] = r1; bt[1][0] = r2; bt[1][1] = r3;
                    ldsm4(r0, r1, r2, r3, addrB(Bbase, nw * 32 + 16, k0));
                    bt[2][0] = r0; bt[2][1] = r1; bt[3][0] = r2; bt[3][1] = r3;
                }
                #pragma unroll
                for (int nt = 0; nt < 4; nt++)
                    mma_fp16(oacc[nt], a, bt[nt]);
            }
        }
        #pragma unroll
        for (int half = 0; half < 2; half++) {
            int r = mg * 16 + rbase + half * 8;
            if (r < m) {
                float wt = wts[r];
                __half* orow = g_slot_out + (size_t)slots[r] * DIMX;
                #pragma unroll
                for (int nt = 0; nt < 4; nt++) {
                    int col = c * 128 + nw * 32 + nt * 8 + cbase;
                    *reinterpret_cast<__half2*>(orow + col) =
                        __floats2half2_rn(oacc[nt][half * 2]     * wt,
                                          oacc[nt][half * 2 + 1] * wt);
                }
            }
        }
        __syncthreads();
    }
}

// ---------------- kernel 5: combine (fp16 slots) ----------------
__global__ void combine_kernel(float* __restrict__ out) {
    int i = blockIdx.x * 256 + threadIdx.x;    // 4 outputs per thread
    if (i >= NTOK * DIMX / 4) return;
    int t = i >> 7;
    int d4 = i & (DIMX/4 - 1);
    float4 s = make_float4(0.f, 0.f, 0.f, 0.f);
    #pragma unroll
    for (int sl = 0; sl < KSLOT; sl++) {
        const __half2* p = reinterpret_cast<const __half2*>(
            &g_slot_out[((size_t)(t * KSLOT + sl)) * DIMX + d4 * 4]);
        float2 a = __half22float2(p[0]);
        float2 b = __half22float2(p[1]);
        s.x += a.x; s.y += a.y; s.z += b.x; s.w += b.y;
    }
    reinterpret_cast<float4*>(out)[i] = s;
}

// ---------------- launch ----------------
extern "C" void kernel_launch(void* const* d_in, const int* in_sizes, int n_in,
                              void* d_out, int out_size) {
    const float* x  = (const float*)d_in[0];
    const float* gw = (const float*)d_in[1];
    const float* gb = (const float*)d_in[2];
    const float* w1 = (const float*)d_in[3];
    const float* w2 = (const float*)d_in[4];
    const float* w3 = (const float*)d_in[5];
    float* out = (float*)d_out;

    const int ffn_smem = 57344;   // A 16K + B 32K + G 8K
    cudaFuncSetAttribute(ffn_mma_kernel,
                         cudaFuncAttributeMaxDynamicSharedMemorySize, ffn_smem);

    prepgate_kernel<<<1600, 256>>>(x, w1, w3, w2, gw, gb);
    scatscan_kernel<<<33, 256>>>();
    ffn_mma_kernel<<<MAXTILES, 256, ffn_smem>>>();
    combine_kernel<<<(NTOK * DIMX / 4) / 256, 256>>>(out);
}